// round 13
// baseline (speedup 1.0000x reference)
#include <cuda_runtime.h>
#include <cuda_bf16.h>
#include <cstdint>
#include <math.h>

#define MB   64
#define C    24
#define S2   64
#define QS   128
#define H    256
#define OUT  28

#define NTHREADS 256

// k_g smem layout (bytes)
#define SB_BIAS  0                       // 3*256 floats = 3072
#define SB_SGW   3072                    // 256 floats   = 1024
#define SB_HA    4096                    // 128 * 528    = 67584
#define SB_WS    71680                   // 3 * 36864    = 110592
#define SB_TOTAL 182272
#define WSLAB    36864                   // one K64 chunk: 256 rows * 144 B

// ---------------- scratch ----------------
__device__ float g_u[MB * S2 * H];
__device__ float g_v[MB * S2 * H];
__device__ float g_w[MB * H];
__device__ float g_xg[MB * H];
__device__ __align__(16) __nv_bfloat16 g_Wb[3 * H * H];

// ---------------- helpers ----------------
__device__ __forceinline__ uint32_t smem_u32(const void* p) {
    uint32_t a;
    asm("{ .reg .u64 t; cvta.to.shared.u64 t, %1; cvt.u32.u64 %0, t; }" : "=r"(a) : "l"(p));
    return a;
}
__device__ __forceinline__ void cp16(uint32_t dst, const void* src) {
    asm volatile("cp.async.ca.shared.global [%0], [%1], 16;" :: "r"(dst), "l"(src) : "memory");
}
__device__ __forceinline__ void cp_commit() {
    asm volatile("cp.async.commit_group;" ::: "memory");
}
__device__ __forceinline__ void ldm_x4(uint32_t* r, uint32_t addr) {
    asm volatile("ldmatrix.sync.aligned.m8n8.x4.shared.b16 {%0,%1,%2,%3}, [%4];"
                 : "=r"(r[0]), "=r"(r[1]), "=r"(r[2]), "=r"(r[3]) : "r"(addr));
}
__device__ __forceinline__ void mma_bf16(float* d, const uint32_t* a, const uint32_t* b) {
    asm volatile(
        "mma.sync.aligned.m16n8k16.row.col.f32.bf16.bf16.f32 "
        "{%0,%1,%2,%3}, {%4,%5,%6,%7}, {%8,%9}, {%0,%1,%2,%3};"
        : "+f"(d[0]), "+f"(d[1]), "+f"(d[2]), "+f"(d[3])
        : "r"(a[0]), "r"(a[1]), "r"(a[2]), "r"(a[3]), "r"(b[0]), "r"(b[1]));
}
__device__ __forceinline__ uint32_t bf2u(float a, float b) {
    __nv_bfloat162 h = __floats2bfloat162_rn(a, b);
    return *(uint32_t*)&h;
}

// =====================================================================
// k_prep: fused  [0,192): W->bf16   [192,256): qw   [256,512): uv
// =====================================================================
__global__ void k_prep(const float* __restrict__ x, const float* __restrict__ qst,
                       const float* __restrict__ Wg1, const float* __restrict__ bg1,
                       const float* __restrict__ W2, const float* __restrict__ W3,
                       const float* __restrict__ W4) {
    const int bid = blockIdx.x, tid = threadIdx.x;

    if (bid < 192) {
        int l = bid >> 6, blk = bid & 63;
        const float* W = (l == 0) ? W2 : (l == 1) ? W3 : W4;
        int i = (blk * 256 + tid) * 4;
        float4 v = *(const float4*)(W + i);
        uint2 o;
        o.x = bf2u(v.x, v.y);
        o.y = bf2u(v.z, v.w);
        *(uint2*)(g_Wb + l * H * H + i) = o;
        return;
    }
    if (bid < 256) {
        int b = bid - 192;
        int lane = tid & 31, w = tid >> 5;
        __shared__ float qs[QS];
        if (tid < QS) qs[tid] = qst[b * QS + tid];
        __syncthreads();
        for (int i = 0; i < 32; i++) {
            int n = w * 32 + i;
            const float* wr = Wg1 + n * 180 + 52;
            float p = 0.0f;
#pragma unroll
            for (int j = 0; j < 4; j++) p += qs[lane + 32 * j] * wr[lane + 32 * j];
#pragma unroll
            for (int off = 16; off > 0; off >>= 1) p += __shfl_xor_sync(0xffffffffu, p, off);
            if (lane == 0) g_w[b * H + n] = p + bg1[n];
        }
        return;
    }
    {
        int idx = bid - 256;
        int b = idx >> 2, seg = idx & 3;
        __shared__ float xf[16][26];
        for (int i = tid; i < 16 * C; i += 256) {
            int c = i / 16, sl = i % 16;
            xf[sl][c] = x[(b * C + c) * S2 + seg * 16 + sl];
        }
        if (tid < 16) {
            int s = seg * 16 + tid;
            xf[tid][24] = ((s >> 3) - 4) * 0.25f;
            xf[tid][25] = ((s & 7) - 4) * 0.25f;
        }
        if (seg == 0) g_xg[b * H + tid] = 0.0f;
        __syncthreads();

        const int n = tid;
        const float* wr = Wg1 + n * 180;
        float Wi[26], Wj[26];
#pragma unroll
        for (int c = 0; c < 26; c++) { Wi[c] = wr[c]; Wj[c] = wr[26 + c]; }
        for (int sl = 0; sl < 16; sl++) {
            float su = 0.0f, sv = 0.0f;
#pragma unroll
            for (int c = 0; c < 26; c++) {
                float xv = xf[sl][c];
                su += xv * Wi[c];
                sv += xv * Wj[c];
            }
            int s = seg * 16 + sl;
            g_u[(b * S2 + s) * H + n] = su;
            g_v[(b * S2 + s) * H + n] = sv;
        }
    }
}

// =====================================================================
// k_g: bf16 mma.sync g-MLP.  CTA = (2 p-rows, batch): M=128,N=256,K=256.
//   8 warps 2(m:64) x 4(n:64).  3-slab weight rotation (1 group-bar/chunk);
//   h1 built K-chunk-wise, overlapped with MMA of previous chunk.
// =====================================================================
__global__ void __launch_bounds__(NTHREADS, 1)
k_g(const float* __restrict__ bg2, const float* __restrict__ bg3,
    const float* __restrict__ bg4) {
    extern __shared__ char smem[];
    float* sbias = (float*)(smem + SB_BIAS);
    float* sgw   = (float*)(smem + SB_SGW);

    const int b = blockIdx.y, tile = blockIdx.x;   // tile: 2 p-rows
    const int tid = threadIdx.x, wid = tid >> 5, lane = tid & 31;
    const int mbase = (wid & 1) * 64;
    const int ng = wid >> 1;                       // n-group 0..3 (2 warps)
    const int nbase = ng * 64;
    const int wtid = tid & 63;

    const uint32_t smA = smem_u32(smem + SB_HA);
    const uint32_t smW = smem_u32(smem + SB_WS);

    const uint32_t aBase = smA + (uint32_t)(mbase + (lane & 15)) * 528 + (uint32_t)(lane >> 4) * 16;
    const uint32_t bOff  = (uint32_t)(((lane >> 4) * 8 + (lane & 7)) * 144 + ((lane >> 3) & 1) * 16);

    // stage chunk c into slab c%3 (per n-group rows [nbase, nbase+64))
    auto stage = [&](int c) {
        const int L = c >> 2, kc = c & 3;
        const __nv_bfloat16* Wb = g_Wb + L * H * H + kc * 64;
        const uint32_t dst = smW + (uint32_t)(c % 3) * WSLAB;
#pragma unroll
        for (int it = 0; it < 8; it++) {
            int idx = wtid + it * 64;              // 0..511
            int nl = idx >> 3, k8 = idx & 7;
            int n = nbase + nl;
            cp16(dst + (uint32_t)(n * 144 + k8 * 16), Wb + n * H + k8 * 8);
        }
        cp_commit();
    };

    stage(0);
    stage(1);

    // biases + g_w into smem
    if (tid < 256) {
        sbias[tid]       = bg2[tid];
        sbias[256 + tid] = bg3[tid];
        sbias[512 + tid] = bg4[tid];
        sgw[tid]         = g_w[b * H + tid];
    }
    __syncthreads();

    // ---- h1 builder for one K-chunk (cols [ck*64, ck*64+64), all 128 rows) ----
    const float* ub = g_u + b * S2 * H;
    const float* vb = g_v + b * S2 * H;
    auto build = [&](int ck) {
#pragma unroll
        for (int it = 0; it < 4; it++) {
            int j = tid + it * NTHREADS;           // 0..1023
            int r = j >> 3;
            int kb = ck * 64 + (j & 7) * 8;
            int q = r & 63, p = tile * 2 + (r >> 6);
            float4 u0 = *(const float4*)(ub + q * H + kb);
            float4 u1 = *(const float4*)(ub + q * H + kb + 4);
            float4 v0 = *(const float4*)(vb + p * H + kb);
            float4 v1 = *(const float4*)(vb + p * H + kb + 4);
            const float* w = sgw + kb;
            uint4 o;
            o.x = bf2u(fmaxf(u0.x + v0.x + w[0], 0.0f), fmaxf(u0.y + v0.y + w[1], 0.0f));
            o.y = bf2u(fmaxf(u0.z + v0.z + w[2], 0.0f), fmaxf(u0.w + v0.w + w[3], 0.0f));
            o.z = bf2u(fmaxf(u1.x + v1.x + w[4], 0.0f), fmaxf(u1.y + v1.y + w[5], 0.0f));
            o.w = bf2u(fmaxf(u1.z + v1.z + w[6], 0.0f), fmaxf(u1.w + v1.w + w[7], 0.0f));
            *(uint4*)(smem + SB_HA + r * 528 + kb * 2) = o;
        }
    };

    build(0);
    __syncthreads();

    float acc[4][8][4];
#pragma unroll
    for (int mt = 0; mt < 4; mt++)
#pragma unroll
        for (int nt = 0; nt < 8; nt++)
#pragma unroll
            for (int i = 0; i < 4; i++) acc[mt][nt][i] = 0.0f;

    for (int c = 0; c < 12; c++) {
        const int kc = c & 3;

        // own commits for chunk c retired (partner handled by group bar)
        if (c <= 10) { asm volatile("cp.async.wait_group 1;" ::: "memory"); }
        else         { asm volatile("cp.async.wait_group 0;" ::: "memory"); }
        asm volatile("bar.sync %0, 64;" :: "r"(ng + 1) : "memory");
        if (c <= 9) stage(c + 2);   // slab (c+2)%3: group's reads done at chunk c-1

        const uint32_t wbuf = smW + (uint32_t)(c % 3) * WSLAB;
#pragma unroll
        for (int kk = 0; kk < 4; kk++) {
            const uint32_t kgA = (uint32_t)(kc * 64 + kk * 16) * 2;
            uint32_t a[4][4];
#pragma unroll
            for (int mt = 0; mt < 4; mt++)
                ldm_x4(a[mt], aBase + (uint32_t)(mt * 16) * 528 + kgA);
#pragma unroll
            for (int i = 0; i < 4; i++) {
                uint32_t r[4];
                ldm_x4(r, wbuf + (uint32_t)(nbase + i * 16) * 144 + (uint32_t)(kk * 32) + bOff);
#pragma unroll
                for (int mt = 0; mt < 4; mt++) {
                    mma_bf16(acc[mt][2 * i],     a[mt], r);
                    mma_bf16(acc[mt][2 * i + 1], a[mt], r + 2);
                }
            }
        }

        // layer-0: build next h1 K-chunk behind this chunk's MMAs
        if (c < 3) {
            build(c + 1);
            __syncthreads();
        }

        if (kc == 3) {          // ---- layer boundary ----
            const int L = c >> 2;
            const float* sb = sbias + L * 256;
            if (L < 2) {
                __syncthreads();   // all reads of hA (layer L) complete
#pragma unroll
                for (int mt = 0; mt < 4; mt++) {
                    const int r0 = mbase + mt * 16 + (lane >> 2);
#pragma unroll
                    for (int nt = 0; nt < 8; nt++) {
                        const int col = nbase + nt * 8 + 2 * (lane & 3);
                        const float b0 = sb[col], b1 = sb[col + 1];
                        *(uint32_t*)(smem + SB_HA + r0 * 528 + col * 2) =
                            bf2u(fmaxf(acc[mt][nt][0] + b0, 0.0f), fmaxf(acc[mt][nt][1] + b1, 0.0f));
                        *(uint32_t*)(smem + SB_HA + (r0 + 8) * 528 + col * 2) =
                            bf2u(fmaxf(acc[mt][nt][2] + b0, 0.0f), fmaxf(acc[mt][nt][3] + b1, 0.0f));
                    }
                }
#pragma unroll
                for (int mt = 0; mt < 4; mt++)
#pragma unroll
                    for (int nt = 0; nt < 8; nt++)
#pragma unroll
                        for (int i = 0; i < 4; i++) acc[mt][nt][i] = 0.0f;
                __syncthreads();   // hA(L+1) visible before reads
            } else {
                // layer 4: relu + column sums -> atomicAdd
                __syncthreads();
                float* red = (float*)(smem + SB_HA);   // [2][256]
#pragma unroll
                for (int nt = 0; nt < 8; nt++) {
                    const int col = nbase + nt * 8 + 2 * (lane & 3);
                    const float b0 = sb[col], b1 = sb[col + 1];
                    float s0 = 0.0f, s1 = 0.0f;
#pragma unroll
                    for (int mt = 0; mt < 4; mt++) {
                        s0 += fmaxf(acc[mt][nt][0] + b0, 0.0f) + fmaxf(acc[mt][nt][2] + b0, 0.0f);
                        s1 += fmaxf(acc[mt][nt][1] + b1, 0.0f) + fmaxf(acc[mt][nt][3] + b1, 0.0f);
                    }
#pragma unroll
                    for (int off = 4; off <= 16; off <<= 1) {
                        s0 += __shfl_xor_sync(0xffffffffu, s0, off);
                        s1 += __shfl_xor_sync(0xffffffffu, s1, off);
                    }
                    if (lane < 4) {
                        red[(wid & 1) * H + col] = s0;
                        red[(wid & 1) * H + col + 1] = s1;
                    }
                }
                __syncthreads();
                if (tid < H) atomicAdd(&g_xg[b * H + tid], red[tid] + red[H + tid]);
            }
        }
    }
}

// =====================================================================
// k_f: f-MLP + log_softmax
// =====================================================================
__global__ void k_f(const float* __restrict__ Wf1, const float* __restrict__ bf1,
                    const float* __restrict__ Wf2, const float* __restrict__ bf2,
                    const float* __restrict__ Wf3, const float* __restrict__ bf3,
                    float* __restrict__ out) {
    int b = blockIdx.x;
    int tid = threadIdx.x, lane = tid & 31, w = tid >> 5;

    __shared__ float xs[H], f1s[H], f2s[H], ls[32];

    xs[tid] = g_xg[b * H + tid];
    __syncthreads();

    for (int i = 0; i < 32; i++) {
        int n = w * 32 + i;
        float p = 0.0f;
#pragma unroll
        for (int j = 0; j < 8; j++) { int k = lane + 32 * j; p += xs[k] * Wf1[n * H + k]; }
#pragma unroll
        for (int off = 16; off > 0; off >>= 1) p += __shfl_xor_sync(0xffffffffu, p, off);
        if (lane == 0) f1s[n] = fmaxf(p + bf1[n], 0.0f);
    }
    __syncthreads();

    for (int i = 0; i < 32; i++) {
        int n = w * 32 + i;
        float p = 0.0f;
#pragma unroll
        for (int j = 0; j < 8; j++) { int k = lane + 32 * j; p += f1s[k] * Wf2[n * H + k]; }
#pragma unroll
        for (int off = 16; off > 0; off >>= 1) p += __shfl_xor_sync(0xffffffffu, p, off);
        if (lane == 0) f2s[n] = fmaxf(p + bf2[n], 0.0f);
    }
    __syncthreads();

    for (int i = 0; i < 4; i++) {
        int n = w * 4 + i;
        if (n < OUT) {
            float p = 0.0f;
#pragma unroll
            for (int j = 0; j < 8; j++) { int k = lane + 32 * j; p += f2s[k] * Wf3[n * H + k]; }
#pragma unroll
            for (int off = 16; off > 0; off >>= 1) p += __shfl_xor_sync(0xffffffffu, p, off);
            if (lane == 0) ls[n] = p + bf3[n];
        }
    }
    __syncthreads();

    if (w == 0) {
        float v = (lane < OUT) ? ls[lane] : -3.4e38f;
        float m = v;
#pragma unroll
        for (int off = 16; off > 0; off >>= 1) m = fmaxf(m, __shfl_xor_sync(0xffffffffu, m, off));
        float e = (lane < OUT) ? expf(v - m) : 0.0f;
        float s = e;
#pragma unroll
        for (int off = 16; off > 0; off >>= 1) s += __shfl_xor_sync(0xffffffffu, s, off);
        float lse = logf(s) + m;
        if (lane < OUT) out[b * OUT + lane] = v - lse;
    }
}

// =====================================================================
extern "C" void kernel_launch(void* const* d_in, const int* in_sizes, int n_in,
                              void* d_out, int out_size) {
    (void)in_sizes; (void)n_in; (void)out_size;
    const float* x   = (const float*)d_in[0];
    const float* qst = (const float*)d_in[1];
    const float* Wg1 = (const float*)d_in[2];
    const float* bg1 = (const float*)d_in[3];
    const float* Wg2 = (const float*)d_in[4];
    const float* bg2 = (const float*)d_in[5];
    const float* Wg3 = (const float*)d_in[6];
    const float* bg3 = (const float*)d_in[7];
    const float* Wg4 = (const float*)d_in[8];
    const float* bg4 = (const float*)d_in[9];
    const float* Wf1 = (const float*)d_in[10];
    const float* bf1 = (const float*)d_in[11];
    const float* Wf2 = (const float*)d_in[12];
    const float* bf2 = (const float*)d_in[13];
    const float* Wf3 = (const float*)d_in[14];
    const float* bf3 = (const float*)d_in[15];

    cudaFuncSetAttribute(k_g, cudaFuncAttributeMaxDynamicSharedMemorySize, SB_TOTAL);

    k_prep<<<512, 256>>>(x, qst, Wg1, bg1, Wg2, Wg3, Wg4);
    k_g<<<dim3(S2 * S2 / 128, MB), NTHREADS, SB_TOTAL>>>(bg2, bg3, bg4);
    k_f<<<MB, 256>>>(Wf1, bf1, Wf2, bf2, Wf3, bf3, (float*)d_out);
}

// round 14
// speedup vs baseline: 1.7634x; 1.7634x over previous
#include <cuda_runtime.h>
#include <cuda_bf16.h>
#include <cstdint>
#include <math.h>

#define MB   64
#define C    24
#define S2   64
#define QS   128
#define H    256
#define OUT  28

#define NTHREADS 256

// k_g smem layout (bytes)
#define SB_BIAS  0                       // 3*256 floats = 3072
#define SB_SGW   3072                    // 128 bf16x2   = 512
#define SB_HA    4096                    // 128 * 528    = 67584
#define SB_WS    71680                   // 2 * 36864    = 73728
#define SB_TOTAL 145408
#define WSLAB    36864                   // one K64 chunk: 256 rows * 144 B

// ---------------- scratch ----------------
__device__ __align__(16) __nv_bfloat16 g_ub[MB * S2 * H];
__device__ __align__(16) __nv_bfloat16 g_vb[MB * S2 * H];
__device__ float g_w[MB * H];
__device__ float g_xg[MB * H];
__device__ __align__(16) __nv_bfloat16 g_Wb[3 * H * H];

// ---------------- helpers ----------------
__device__ __forceinline__ uint32_t smem_u32(const void* p) {
    uint32_t a;
    asm("{ .reg .u64 t; cvta.to.shared.u64 t, %1; cvt.u32.u64 %0, t; }" : "=r"(a) : "l"(p));
    return a;
}
__device__ __forceinline__ void cp16(uint32_t dst, const void* src) {
    asm volatile("cp.async.ca.shared.global [%0], [%1], 16;" :: "r"(dst), "l"(src) : "memory");
}
__device__ __forceinline__ void cp_commit() {
    asm volatile("cp.async.commit_group;" ::: "memory");
}
__device__ __forceinline__ void ldm_x4(uint32_t* r, uint32_t addr) {
    asm volatile("ldmatrix.sync.aligned.m8n8.x4.shared.b16 {%0,%1,%2,%3}, [%4];"
                 : "=r"(r[0]), "=r"(r[1]), "=r"(r[2]), "=r"(r[3]) : "r"(addr));
}
__device__ __forceinline__ void mma_bf16(float* d, const uint32_t* a, const uint32_t* b) {
    asm volatile(
        "mma.sync.aligned.m16n8k16.row.col.f32.bf16.bf16.f32 "
        "{%0,%1,%2,%3}, {%4,%5,%6,%7}, {%8,%9}, {%0,%1,%2,%3};"
        : "+f"(d[0]), "+f"(d[1]), "+f"(d[2]), "+f"(d[3])
        : "r"(a[0]), "r"(a[1]), "r"(a[2]), "r"(a[3]), "r"(b[0]), "r"(b[1]));
}
__device__ __forceinline__ uint32_t bf2u(float a, float b) {
    __nv_bfloat162 h = __floats2bfloat162_rn(a, b);
    return *(uint32_t*)&h;
}
// packed relu(a + b + w)
__device__ __forceinline__ uint32_t hfuse(uint32_t ua, uint32_t uv, uint32_t uw) {
    __nv_bfloat162 a = *(__nv_bfloat162*)&ua;
    __nv_bfloat162 v = *(__nv_bfloat162*)&uv;
    __nv_bfloat162 w = *(__nv_bfloat162*)&uw;
    __nv_bfloat162 z = __floats2bfloat162_rn(0.0f, 0.0f);
    __nv_bfloat162 r = __hmax2(__hadd2(__hadd2(a, v), w), z);
    return *(uint32_t*)&r;
}

// =====================================================================
// k_prep: fused  [0,192): W->bf16   [192,256): qw   [256,512): uv
// =====================================================================
__global__ void k_prep(const float* __restrict__ x, const float* __restrict__ qst,
                       const float* __restrict__ Wg1, const float* __restrict__ bg1,
                       const float* __restrict__ W2, const float* __restrict__ W3,
                       const float* __restrict__ W4) {
    const int bid = blockIdx.x, tid = threadIdx.x;

    if (bid < 192) {
        int l = bid >> 6, blk = bid & 63;
        const float* W = (l == 0) ? W2 : (l == 1) ? W3 : W4;
        int i = (blk * 256 + tid) * 4;
        float4 v = *(const float4*)(W + i);
        uint2 o;
        o.x = bf2u(v.x, v.y);
        o.y = bf2u(v.z, v.w);
        *(uint2*)(g_Wb + l * H * H + i) = o;
        return;
    }
    if (bid < 256) {
        int b = bid - 192;
        int lane = tid & 31, w = tid >> 5;
        __shared__ float qs[QS];
        if (tid < QS) qs[tid] = qst[b * QS + tid];
        __syncthreads();
        for (int i = 0; i < 32; i++) {
            int n = w * 32 + i;
            const float* wr = Wg1 + n * 180 + 52;
            float p = 0.0f;
#pragma unroll
            for (int j = 0; j < 4; j++) p += qs[lane + 32 * j] * wr[lane + 32 * j];
#pragma unroll
            for (int off = 16; off > 0; off >>= 1) p += __shfl_xor_sync(0xffffffffu, p, off);
            if (lane == 0) g_w[b * H + n] = p + bg1[n];
        }
        return;
    }
    {
        int idx = bid - 256;
        int b = idx >> 2, seg = idx & 3;
        __shared__ float xf[16][26];
        for (int i = tid; i < 16 * C; i += 256) {
            int c = i / 16, sl = i % 16;
            xf[sl][c] = x[(b * C + c) * S2 + seg * 16 + sl];
        }
        if (tid < 16) {
            int s = seg * 16 + tid;
            xf[tid][24] = ((s >> 3) - 4) * 0.25f;
            xf[tid][25] = ((s & 7) - 4) * 0.25f;
        }
        if (seg == 0) g_xg[b * H + tid] = 0.0f;
        __syncthreads();

        const int n = tid;
        const float* wr = Wg1 + n * 180;
        float Wi[26], Wj[26];
#pragma unroll
        for (int c = 0; c < 26; c++) { Wi[c] = wr[c]; Wj[c] = wr[26 + c]; }
        for (int sl = 0; sl < 16; sl++) {
            float su = 0.0f, sv = 0.0f;
#pragma unroll
            for (int c = 0; c < 26; c++) {
                float xv = xf[sl][c];
                su += xv * Wi[c];
                sv += xv * Wj[c];
            }
            int s = seg * 16 + sl;
            g_ub[(b * S2 + s) * H + n] = __float2bfloat16_rn(su);
            g_vb[(b * S2 + s) * H + n] = __float2bfloat16_rn(sv);
        }
    }
}

// =====================================================================
// k_g: bf16 mma.sync g-MLP.  CTA = (2 p-rows, batch): M=128,N=256,K=256.
//   8 warps 2(m:64) x 4(n:64), warp tile 64x64.  (R12 structure.)
// =====================================================================
__global__ void __launch_bounds__(NTHREADS, 1)
k_g(const float* __restrict__ bg2, const float* __restrict__ bg3,
    const float* __restrict__ bg4) {
    extern __shared__ char smem[];
    float* sbias = (float*)(smem + SB_BIAS);
    uint32_t* sgw2 = (uint32_t*)(smem + SB_SGW);   // 128 packed bf16x2

    const int b = blockIdx.y, tile = blockIdx.x;   // tile: 2 p-rows
    const int tid = threadIdx.x, wid = tid >> 5, lane = tid & 31;
    const int mbase = (wid & 1) * 64;
    const int ng = wid >> 1;                       // n-group 0..3 (2 warps)
    const int nbase = ng * 64;
    const int wtid = tid & 63;

    const uint32_t smA = smem_u32(smem + SB_HA);
    const uint32_t smW = smem_u32(smem + SB_WS);

    const uint32_t aBase = smA + (uint32_t)(mbase + (lane & 15)) * 528 + (uint32_t)(lane >> 4) * 16;
    const uint32_t bOff  = (uint32_t)(((lane >> 4) * 8 + (lane & 7)) * 144 + ((lane >> 3) & 1) * 16);

    // stage chunk c into slab c&1 (per n-group rows [nbase, nbase+64))
    auto stage = [&](int c) {
        const int L = c >> 2, kc = c & 3;
        const __nv_bfloat16* Wb = g_Wb + L * H * H + kc * 64;
        const uint32_t dst = smW + (uint32_t)(c & 1) * WSLAB;
#pragma unroll
        for (int it = 0; it < 8; it++) {
            int idx = wtid + it * 64;              // 0..511
            int nl = idx >> 3, k8 = idx & 7;
            int n = nbase + nl;
            cp16(dst + (uint32_t)(n * 144 + k8 * 16), Wb + n * H + k8 * 8);
        }
        cp_commit();
    };

    stage(0);
    stage(1);

    // biases + packed g_w into smem
    if (tid < 256) {
        sbias[tid]       = bg2[tid];
        sbias[256 + tid] = bg3[tid];
        sbias[512 + tid] = bg4[tid];
    }
    if (tid < 128) {
        sgw2[tid] = bf2u(g_w[b * H + 2 * tid], g_w[b * H + 2 * tid + 1]);
    }
    __syncthreads();

    // ---- build h1 = relu(u[q] + v[p] + w) packed bf16 (128 rows) ----
    const __nv_bfloat16* ub = g_ub + b * S2 * H;
    const __nv_bfloat16* vb = g_vb + b * S2 * H;
#pragma unroll
    for (int it = 0; it < 16; it++) {
        int i = tid + it * NTHREADS;               // 0..4095
        int r = i >> 5, kb = (i & 31) * 8;
        int q = r & 63, p = tile * 2 + (r >> 6);
        uint4 uu = *(const uint4*)(ub + q * H + kb);
        uint4 vv = *(const uint4*)(vb + p * H + kb);
        const uint32_t* w2 = sgw2 + (kb >> 1);
        uint4 o;
        o.x = hfuse(uu.x, vv.x, w2[0]);
        o.y = hfuse(uu.y, vv.y, w2[1]);
        o.z = hfuse(uu.z, vv.z, w2[2]);
        o.w = hfuse(uu.w, vv.w, w2[3]);
        *(uint4*)(smem + SB_HA + r * 528 + kb * 2) = o;
    }
    __syncthreads();

    float acc[4][8][4];
#pragma unroll
    for (int mt = 0; mt < 4; mt++)
#pragma unroll
        for (int nt = 0; nt < 8; nt++)
#pragma unroll
            for (int i = 0; i < 4; i++) acc[mt][nt][i] = 0.0f;

    for (int c = 0; c < 12; c++) {
        const int kc = c & 3;

        if (c <= 10) { asm volatile("cp.async.wait_group 1;" ::: "memory"); }
        else         { asm volatile("cp.async.wait_group 0;" ::: "memory"); }
        asm volatile("bar.sync %0, 64;" :: "r"(ng + 1) : "memory");

        const uint32_t wbuf = smW + (uint32_t)(c & 1) * WSLAB;
#pragma unroll
        for (int kk = 0; kk < 4; kk++) {
            const uint32_t kgA = (uint32_t)(kc * 64 + kk * 16) * 2;
            uint32_t a[4][4];
#pragma unroll
            for (int mt = 0; mt < 4; mt++)
                ldm_x4(a[mt], aBase + (uint32_t)(mt * 16) * 528 + kgA);
#pragma unroll
            for (int i = 0; i < 4; i++) {
                uint32_t r[4];
                ldm_x4(r, wbuf + (uint32_t)(nbase + i * 16) * 144 + (uint32_t)(kk * 32) + bOff);
#pragma unroll
                for (int mt = 0; mt < 4; mt++) {
                    mma_bf16(acc[mt][2 * i],     a[mt], r);
                    mma_bf16(acc[mt][2 * i + 1], a[mt], r + 2);
                }
            }
        }

        if (c + 2 < 12) {
            asm volatile("bar.sync %0, 64;" :: "r"(ng + 1) : "memory");
            stage(c + 2);
        }

        if (kc == 3) {          // ---- layer boundary ----
            const int L = c >> 2;
            const float* sb = sbias + L * 256;
            if (L < 2) {
                __syncthreads();   // all reads of hA (layer L) complete
#pragma unroll
                for (int mt = 0; mt < 4; mt++) {
                    const int r0 = mbase + mt * 16 + (lane >> 2);
#pragma unroll
                    for (int nt = 0; nt < 8; nt++) {
                        const int col = nbase + nt * 8 + 2 * (lane & 3);
                        const float b0 = sb[col], b1 = sb[col + 1];
                        *(uint32_t*)(smem + SB_HA + r0 * 528 + col * 2) =
                            bf2u(fmaxf(acc[mt][nt][0] + b0, 0.0f), fmaxf(acc[mt][nt][1] + b1, 0.0f));
                        *(uint32_t*)(smem + SB_HA + (r0 + 8) * 528 + col * 2) =
                            bf2u(fmaxf(acc[mt][nt][2] + b0, 0.0f), fmaxf(acc[mt][nt][3] + b1, 0.0f));
                    }
                }
#pragma unroll
                for (int mt = 0; mt < 4; mt++)
#pragma unroll
                    for (int nt = 0; nt < 8; nt++)
#pragma unroll
                        for (int i = 0; i < 4; i++) acc[mt][nt][i] = 0.0f;
                __syncthreads();   // hA(L+1) visible before reads
            } else {
                // layer 4: relu + column sums -> atomicAdd
                __syncthreads();
                float* red = (float*)(smem + SB_HA);   // [2][256]
#pragma unroll
                for (int nt = 0; nt < 8; nt++) {
                    const int col = nbase + nt * 8 + 2 * (lane & 3);
                    const float b0 = sb[col], b1 = sb[col + 1];
                    float s0 = 0.0f, s1 = 0.0f;
#pragma unroll
                    for (int mt = 0; mt < 4; mt++) {
                        s0 += fmaxf(acc[mt][nt][0] + b0, 0.0f) + fmaxf(acc[mt][nt][2] + b0, 0.0f);
                        s1 += fmaxf(acc[mt][nt][1] + b1, 0.0f) + fmaxf(acc[mt][nt][3] + b1, 0.0f);
                    }
#pragma unroll
                    for (int off = 4; off <= 16; off <<= 1) {
                        s0 += __shfl_xor_sync(0xffffffffu, s0, off);
                        s1 += __shfl_xor_sync(0xffffffffu, s1, off);
                    }
                    if (lane < 4) {
                        red[(wid & 1) * H + col] = s0;
                        red[(wid & 1) * H + col + 1] = s1;
                    }
                }
                __syncthreads();
                if (tid < H) atomicAdd(&g_xg[b * H + tid], red[tid] + red[H + tid]);
            }
        }
    }
}

// =====================================================================
// k_f: f-MLP + log_softmax
// =====================================================================
__global__ void k_f(const float* __restrict__ Wf1, const float* __restrict__ bf1,
                    const float* __restrict__ Wf2, const float* __restrict__ bf2,
                    const float* __restrict__ Wf3, const float* __restrict__ bf3,
                    float* __restrict__ out) {
    int b = blockIdx.x;
    int tid = threadIdx.x, lane = tid & 31, w = tid >> 5;

    __shared__ float xs[H], f1s[H], f2s[H], ls[32];

    xs[tid] = g_xg[b * H + tid];
    __syncthreads();

    for (int i = 0; i < 32; i++) {
        int n = w * 32 + i;
        float p = 0.0f;
#pragma unroll
        for (int j = 0; j < 8; j++) { int k = lane + 32 * j; p += xs[k] * Wf1[n * H + k]; }
#pragma unroll
        for (int off = 16; off > 0; off >>= 1) p += __shfl_xor_sync(0xffffffffu, p, off);
        if (lane == 0) f1s[n] = fmaxf(p + bf1[n], 0.0f);
    }
    __syncthreads();

    for (int i = 0; i < 32; i++) {
        int n = w * 32 + i;
        float p = 0.0f;
#pragma unroll
        for (int j = 0; j < 8; j++) { int k = lane + 32 * j; p += f1s[k] * Wf2[n * H + k]; }
#pragma unroll
        for (int off = 16; off > 0; off >>= 1) p += __shfl_xor_sync(0xffffffffu, p, off);
        if (lane == 0) f2s[n] = fmaxf(p + bf2[n], 0.0f);
    }
    __syncthreads();

    for (int i = 0; i < 4; i++) {
        int n = w * 4 + i;
        if (n < OUT) {
            float p = 0.0f;
#pragma unroll
            for (int j = 0; j < 8; j++) { int k = lane + 32 * j; p += f2s[k] * Wf3[n * H + k]; }
#pragma unroll
            for (int off = 16; off > 0; off >>= 1) p += __shfl_xor_sync(0xffffffffu, p, off);
            if (lane == 0) ls[n] = p + bf3[n];
        }
    }
    __syncthreads();

    if (w == 0) {
        float v = (lane < OUT) ? ls[lane] : -3.4e38f;
        float m = v;
#pragma unroll
        for (int off = 16; off > 0; off >>= 1) m = fmaxf(m, __shfl_xor_sync(0xffffffffu, m, off));
        float e = (lane < OUT) ? expf(v - m) : 0.0f;
        float s = e;
#pragma unroll
        for (int off = 16; off > 0; off >>= 1) s += __shfl_xor_sync(0xffffffffu, s, off);
        float lse = logf(s) + m;
        if (lane < OUT) out[b * OUT + lane] = v - lse;
    }
}

// =====================================================================
extern "C" void kernel_launch(void* const* d_in, const int* in_sizes, int n_in,
                              void* d_out, int out_size) {
    (void)in_sizes; (void)n_in; (void)out_size;
    const float* x   = (const float*)d_in[0];
    const float* qst = (const float*)d_in[1];
    const float* Wg1 = (const float*)d_in[2];
    const float* bg1 = (const float*)d_in[3];
    const float* Wg2 = (const float*)d_in[4];
    const float* bg2 = (const float*)d_in[5];
    const float* Wg3 = (const float*)d_in[6];
    const float* bg3 = (const float*)d_in[7];
    const float* Wg4 = (const float*)d_in[8];
    const float* bg4 = (const float*)d_in[9];
    const float* Wf1 = (const float*)d_in[10];
    const float* bf1 = (const float*)d_in[11];
    const float* Wf2 = (const float*)d_in[12];
    const float* bf2 = (const float*)d_in[13];
    const float* Wf3 = (const float*)d_in[14];
    const float* bf3 = (const float*)d_in[15];

    cudaFuncSetAttribute(k_g, cudaFuncAttributeMaxDynamicSharedMemorySize, SB_TOTAL);

    k_prep<<<512, 256>>>(x, qst, Wg1, bg1, Wg2, Wg3, Wg4);
    k_g<<<dim3(S2 * S2 / 128, MB), NTHREADS, SB_TOTAL>>>(bg2, bg3, bg4);
    k_f<<<MB, 256>>>(Wf1, bf1, Wf2, bf2, Wf3, bf3, (float*)d_out);
}